// round 9
// baseline (speedup 1.0000x reference)
#include <cuda_runtime.h>
#include <cuda_bf16.h>
#include <math.h>
#include <stdint.h>

// Problem constants
#define BB  2
#define SS  2048
#define EE  2048
#define HH  16
#define DHH 128
#define LL  64
#define MM  (BB*SS)          // 4096 rows for the big GEMMs

#define N_BSE ((size_t)BB*SS*EE)       // 8388608
#define N_LAT ((size_t)BB*HH*SS*LL)    // 4194304

// fp32 scratch: attn_out lives at slot 3 (others now unused but kept for layout stability)
__device__ float g_scratch[5*8388608];
// bf16 split-stacked operands: A' [4096, 6144]; weight slots
__device__ __nv_bfloat16 g_abf[(size_t)4096 * 6144];
__device__ __nv_bfloat16 g_wbf[4][(size_t)2048 * 6144];
// attention operands: qh, ql, kh, kl planes [B,H,S,64]; vh, vl [B,H,S,128]
__device__ __nv_bfloat16 g_qk[4 * 4194304];
__device__ __nv_bfloat16 g_v[2 * 8388608];
// composed latent biases: bc[n] = b @ Wl + bl   (q, k)
__device__ float g_bc[2][1024];

// ===========================================================================
// Helpers
// ===========================================================================
__device__ __forceinline__ uint32_t smem_u32(const void* p) {
    uint32_t a;
    asm("{ .reg .u64 t; cvta.to.shared.u64 t, %1; cvt.u32.u64 %0, t; }"
        : "=r"(a) : "l"(p));
    return a;
}

#define CP_ASYNC16(sm, gp) \
    asm volatile("cp.async.cg.shared.global [%0], [%1], 16;" \
        :: "r"((uint32_t)(sm)), "l"(gp) : "memory")
#define CP_COMMIT() asm volatile("cp.async.commit_group;" ::: "memory")
#define CP_WAIT(n)  asm volatile("cp.async.wait_group %0;" :: "n"(n) : "memory")

// swizzles: 64B rows, 128B rows, 256B rows
#define SWZ64(o)  ((o) ^ (((o) >> 3) & 0x30))
#define SW128(o)  ((o) ^ (((o) >> 3) & 0x70))
#define SW256(o)  ((o) ^ (((o) >> 4) & 0x70))

#define LDMATRIX_X4(r0, r1, r2, r3, addr) \
    asm volatile("ldmatrix.sync.aligned.m8n8.x4.shared.b16 {%0,%1,%2,%3}, [%4];" \
        : "=r"(r0), "=r"(r1), "=r"(r2), "=r"(r3) : "r"(addr))

#define LDMATRIX_X4_T(r0, r1, r2, r3, addr) \
    asm volatile("ldmatrix.sync.aligned.m8n8.x4.trans.shared.b16 {%0,%1,%2,%3}, [%4];" \
        : "=r"(r0), "=r"(r1), "=r"(r2), "=r"(r3) : "r"(addr))

#define MMA_BF16(c, a, b) \
    asm volatile("mma.sync.aligned.m16n8k16.row.col.f32.bf16.bf16.f32 " \
        "{%0,%1,%2,%3}, {%4,%5,%6,%7}, {%8,%9}, {%0,%1,%2,%3};" \
        : "+f"((c)[0]), "+f"((c)[1]), "+f"((c)[2]), "+f"((c)[3]) \
        : "r"((a)[0]), "r"((a)[1]), "r"((a)[2]), "r"((a)[3]), \
          "r"((b)[0]), "r"((b)[1]))

#define MMA_BF16S(c, a, b0, b1) \
    asm volatile("mma.sync.aligned.m16n8k16.row.col.f32.bf16.bf16.f32 " \
        "{%0,%1,%2,%3}, {%4,%5,%6,%7}, {%8,%9}, {%0,%1,%2,%3};" \
        : "+f"((c)[0]), "+f"((c)[1]), "+f"((c)[2]), "+f"((c)[3]) \
        : "r"((a)[0]), "r"((a)[1]), "r"((a)[2]), "r"((a)[3]), \
          "r"(b0), "r"(b1))

__device__ __forceinline__ uint32_t pack_bf16(float lo, float hi) {
    uint32_t r;
    asm("cvt.rn.bf16x2.f32 %0, %1, %2;" : "=r"(r) : "f"(hi), "f"(lo));
    return r;
}

// ===========================================================================
// Conversion kernels
// ===========================================================================
#define GK  6144
#define GKB (GK * 2)   // row stride in bytes

// A' [M, 6144]: cols [0:2048)=hi, [2048:4096)=hi, [4096:6144)=lo
__global__ __launch_bounds__(256)
void conv_a(const float* __restrict__ in, __nv_bfloat16* __restrict__ out) {
    int i4 = (blockIdx.x * 256 + threadIdx.x) * 4;
    int m = i4 >> 11, k = i4 & 2047;
    float4 xv = *(const float4*)(in + (size_t)m * 2048 + k);
    __nv_bfloat16 h[4], l[4];
    float xs[4] = {xv.x, xv.y, xv.z, xv.w};
#pragma unroll
    for (int j = 0; j < 4; j++) {
        h[j] = __float2bfloat16(xs[j]);
        l[j] = __float2bfloat16(xs[j] - __bfloat162float(h[j]));
    }
    size_t base = (size_t)m * GK + k;
    __nv_bfloat162 h01, h23, l01, l23;
    h01.x = h[0]; h01.y = h[1]; h23.x = h[2]; h23.y = h[3];
    l01.x = l[0]; l01.y = l[1]; l23.x = l[2]; l23.y = l[3];
    *(__nv_bfloat162*)(out + base)            = h01;
    *(__nv_bfloat162*)(out + base + 2)        = h23;
    *(__nv_bfloat162*)(out + base + 2048)     = h01;
    *(__nv_bfloat162*)(out + base + 2050)     = h23;
    *(__nv_bfloat162*)(out + base + 4096)     = l01;
    *(__nv_bfloat162*)(out + base + 4098)     = l23;
}

// W [K=2048, N=2048] -> W'^T [N rows, 6144]: cols [0:2048)=hi, [2048:4096)=lo, [4096:6144)=hi
__global__ __launch_bounds__(256)
void conv_w(const float* __restrict__ W, __nv_bfloat16* __restrict__ out) {
    __shared__ float ts[32][33];
    const int tid = threadIdx.x;
    const int tx = tid & 31, ty = tid >> 5;
    const int n0 = blockIdx.x * 32, k0 = blockIdx.y * 32;
#pragma unroll
    for (int it = 0; it < 4; it++)
        ts[ty + it*8][tx] = W[(size_t)(k0 + ty + it*8) * 2048 + n0 + tx];
    __syncthreads();
#pragma unroll
    for (int it = 0; it < 4; it++) {
        int r = ty + it*8;
        float v = ts[tx][r];
        __nv_bfloat16 hi = __float2bfloat16(v);
        __nv_bfloat16 lo = __float2bfloat16(v - __bfloat162float(hi));
        size_t ob = (size_t)(n0 + r) * GK + k0 + tx;
        out[ob]        = hi;
        out[ob + 2048] = lo;
        out[ob + 4096] = hi;
    }
}

// ===========================================================================
// Composed latent weights: Wc^T[n=h*64+l, e] = sum_d Wl[d,l] * Wbig[e, h*128+d]
// written split-stacked [1024, 6144] (hi, lo, hi). grid (16 etiles, 16 heads).
// ===========================================================================
#define WC_SMEM (128*129*4 + 128*64*4)

__global__ __launch_bounds__(256)
void wc_kernel(const float* __restrict__ Wbig, const float* __restrict__ Wl,
               __nv_bfloat16* __restrict__ out) {
    extern __shared__ float wsm[];
    float* wq_s = wsm;              // [128][129]  [i][d]
    float* wl_s = wsm + 128*129;    // [128][64]   [d][l]
    const int tid = threadIdx.x;
    const int e0 = blockIdx.x * 128, h = blockIdx.y;

    for (int idx = tid; idx < 128*128; idx += 256) {
        int i = idx >> 7, d = idx & 127;
        wq_s[i*129 + d] = Wbig[(size_t)(e0 + i) * 2048 + h*128 + d];
    }
    for (int idx = tid; idx < 128*64; idx += 256)
        wl_s[idx] = Wl[idx];
    __syncthreads();

    const int i = tid & 127;
    const int lg = tid >> 7;          // 0..1
#pragma unroll 4
    for (int ll = 0; ll < 32; ll++) {
        int l = lg * 32 + ll;
        float acc = 0.f;
#pragma unroll 8
        for (int d = 0; d < 128; d++)
            acc += wq_s[i*129 + d] * wl_s[d*64 + l];
        __nv_bfloat16 hi = __float2bfloat16(acc);
        __nv_bfloat16 lo = __float2bfloat16(acc - __bfloat162float(hi));
        size_t ob = (size_t)(h*64 + l) * GK + e0 + i;
        out[ob]        = hi;
        out[ob + 2048] = lo;
        out[ob + 4096] = hi;
    }
}

// bc[n] = bl[l] + sum_d bbig[h*128+d] * Wl[d,l]
__global__ __launch_bounds__(256)
void wc_bias(const float* __restrict__ bbig, const float* __restrict__ Wl,
             const float* __restrict__ bl, float* __restrict__ bc) {
    int n = blockIdx.x * 256 + threadIdx.x;
    int h = n >> 6, l = n & 63;
    float acc = bl[l];
    for (int d = 0; d < 128; d++)
        acc += bbig[h*128 + d] * Wl[d*64 + l];
    bc[n] = acc;
}

// ===========================================================================
// mma.sync bf16 GEMM, templated epilogue.
// MODE 0: fp32 C = acc + bias
// MODE 1: vh/vl planes [B,H,S,128]
// MODE 2: elu+1, scale -> qh/ql (or kh/kl) planes [B,H,S,64]
// ===========================================================================
#define KITERS   192
#define STAGE_A  8192
#define STAGE_B  8192
#define B_OFF    (4 * STAGE_A)
#define GEMM_SMEM (B_OFF + 4 * STAGE_B)

template<int MODE>
__global__ __launch_bounds__(256, 2)
void gemm_k(const __nv_bfloat16* __restrict__ A, const __nv_bfloat16* __restrict__ Bt,
            const float* __restrict__ bias, float* __restrict__ C,
            __nv_bfloat16* __restrict__ P0, __nv_bfloat16* __restrict__ P1,
            float scale) {
    extern __shared__ char gsm[];
    uint32_t sb = smem_u32(gsm);
    const int tid = threadIdx.x;
    const int wid = tid >> 5, lane = tid & 31;
    const int m0 = blockIdx.y * 128, n0 = blockIdx.x * 128;
    const int wm0 = (wid >> 2) * 64;
    const int wn0 = (wid & 3) * 32;

    const char* Ab = (const char*)A + (size_t)m0 * GKB;
    const char* Bb = (const char*)Bt + (size_t)n0 * GKB;

    const int lr = tid >> 2;
    const int lq = tid & 3;

    auto load_chunk = [&](int j) {
        const int st = j & 3;
        uint32_t ab = sb + st * STAGE_A;
        uint32_t bb = sb + B_OFF + st * STAGE_B;
        const char* ag = Ab + (size_t)j * 64;
        const char* bg = Bb + (size_t)j * 64;
#pragma unroll
        for (int i = 0; i < 2; i++) {
            int r = lr + i * 64;
            CP_ASYNC16(ab + SWZ64(r * 64 + lq * 16), ag + (size_t)r * GKB + lq * 16);
        }
#pragma unroll
        for (int i = 0; i < 2; i++) {
            int r = lr + i * 64;
            CP_ASYNC16(bb + SWZ64(r * 64 + lq * 16), bg + (size_t)r * GKB + lq * 16);
        }
        CP_COMMIT();
    };

    float acc[4][4][4];
#pragma unroll
    for (int mt = 0; mt < 4; mt++)
#pragma unroll
        for (int nt = 0; nt < 4; nt++)
#pragma unroll
            for (int e = 0; e < 4; e++) acc[mt][nt][e] = 0.f;

    load_chunk(0);
    load_chunk(1);
    load_chunk(2);

    const int arow = lane & 15;
    const int acol = (lane >> 4) * 16;

    for (int it = 0; it < KITERS; it++) {
        CP_WAIT(2);
        __syncthreads();

        if (it + 3 < KITERS) load_chunk(it + 3);
        else                 CP_COMMIT();

        const int st = it & 3;
        uint32_t ab = sb + st * STAGE_A;
        uint32_t bb = sb + B_OFF + st * STAGE_B;

#pragma unroll
        for (int kk = 0; kk < 2; kk++) {
            uint32_t a[4][4];
            uint32_t b[4][2];
#pragma unroll
            for (int mt = 0; mt < 4; mt++) {
                uint32_t addr = ab + SWZ64((wm0 + mt*16 + arow) * 64 + kk*32 + acol);
                LDMATRIX_X4(a[mt][0], a[mt][1], a[mt][2], a[mt][3], addr);
            }
#pragma unroll
            for (int nb = 0; nb < 2; nb++) {
                uint32_t r0, r1, r2, r3;
                uint32_t addr = bb + SWZ64((wn0 + nb*16 + arow) * 64 + kk*32 + acol);
                LDMATRIX_X4(r0, r1, r2, r3, addr);
                b[nb*2+0][0] = r0; b[nb*2+0][1] = r2;
                b[nb*2+1][0] = r1; b[nb*2+1][1] = r3;
            }
#pragma unroll
            for (int mt = 0; mt < 4; mt++)
#pragma unroll
                for (int nt = 0; nt < 4; nt++)
                    MMA_BF16(acc[mt][nt], a[mt], b[nt]);
        }
        __syncthreads();
    }

    const int er = lane >> 2, ec = (lane & 3) * 2;
#pragma unroll
    for (int mt = 0; mt < 4; mt++) {
#pragma unroll
        for (int nt = 0; nt < 4; nt++) {
            int col = n0 + wn0 + nt*8 + ec;
            int row0 = m0 + wm0 + mt*16 + er;
            float b0 = bias[col], b1 = bias[col + 1];
            if (MODE == 0) {
                float2 o0, o1;
                o0.x = acc[mt][nt][0] + b0; o0.y = acc[mt][nt][1] + b1;
                o1.x = acc[mt][nt][2] + b0; o1.y = acc[mt][nt][3] + b1;
                *(float2*)(C + (size_t)row0 * 2048 + col)       = o0;
                *(float2*)(C + (size_t)(row0 + 8) * 2048 + col) = o1;
            } else if (MODE == 1) {
                int h = col >> 7, d = col & 127;
#pragma unroll
                for (int rr = 0; rr < 2; rr++) {
                    int row = row0 + rr*8;
                    int b = row >> 11, s = row & 2047;
                    float v0 = acc[mt][nt][rr*2+0] + b0;
                    float v1 = acc[mt][nt][rr*2+1] + b1;
                    __nv_bfloat162 hi2, lo2;
                    hi2.x = __float2bfloat16(v0);
                    hi2.y = __float2bfloat16(v1);
                    lo2.x = __float2bfloat16(v0 - __bfloat162float(hi2.x));
                    lo2.y = __float2bfloat16(v1 - __bfloat162float(hi2.y));
                    size_t ob = (((size_t)(b*HH + h)) * SS + s) * DHH + d;
                    *(__nv_bfloat162*)(P0 + ob) = hi2;
                    *(__nv_bfloat162*)(P1 + ob) = lo2;
                }
            } else {
                int h = col >> 6, l = col & 63;
#pragma unroll
                for (int rr = 0; rr < 2; rr++) {
                    int row = row0 + rr*8;
                    int b = row >> 11, s = row & 2047;
                    float a0 = acc[mt][nt][rr*2+0] + b0;
                    float a1 = acc[mt][nt][rr*2+1] + b1;
                    float r0 = ((a0 > 0.f) ? (a0 + 1.f) : __expf(a0)) * scale;
                    float r1 = ((a1 > 0.f) ? (a1 + 1.f) : __expf(a1)) * scale;
                    __nv_bfloat162 hi2, lo2;
                    hi2.x = __float2bfloat16(r0);
                    hi2.y = __float2bfloat16(r1);
                    lo2.x = __float2bfloat16(r0 - __bfloat162float(hi2.x));
                    lo2.y = __float2bfloat16(r1 - __bfloat162float(hi2.y));
                    size_t ob = (((size_t)(b*HH + h)) * SS + s) * LL + l;
                    *(__nv_bfloat162*)(P0 + ob) = hi2;
                    *(__nv_bfloat162*)(P1 + ob) = lo2;
                }
            }
        }
    }
}

// ===========================================================================
// Tensor-core block attention (unchanged from R6)
// ===========================================================================
#define QH_OFF  0
#define QL_OFF  16384
#define KH_OFF  32768
#define KL_OFF  49152
#define VH_OFF  65536
#define VL_OFF  98304
#define ATT_SMEM 131072
#define NCHN    32

__global__ __launch_bounds__(256, 1)
void attention_mma(const __nv_bfloat16* __restrict__ qh_g, const __nv_bfloat16* __restrict__ ql_g,
                   const __nv_bfloat16* __restrict__ kh_g, const __nv_bfloat16* __restrict__ kl_g,
                   const __nv_bfloat16* __restrict__ vh_g, const __nv_bfloat16* __restrict__ vl_g,
                   float* __restrict__ outp) {
    extern __shared__ char asmem[];
    uint32_t sb = smem_u32(asmem);
    const int tid = threadIdx.x, wid = tid >> 5, lane = tid & 31;
    const int qt = blockIdx.x, h = blockIdx.y, b = blockIdx.z;
    const int qr0 = qt * 128;
    const size_t bh = (size_t)(b * HH + h);

    const char* qhb = (const char*)(qh_g + (bh * SS + qr0) * LL);
    const char* qlb = (const char*)(ql_g + (bh * SS + qr0) * LL);
    const char* khb = (const char*)(kh_g + bh * SS * LL);
    const char* klb = (const char*)(kl_g + bh * SS * LL);
    const char* vhb = (const char*)(vh_g + bh * SS * DHH);
    const char* vlb = (const char*)(vl_g + bh * SS * DHH);

#pragma unroll
    for (int i = 0; i < 4; i++) {
        int e = tid + i * 256;
        int r = e >> 3, c = (e & 7) * 16;
        CP_ASYNC16(sb + QH_OFF + SW128(r * 128 + c), qhb + (size_t)r * 128 + c);
        CP_ASYNC16(sb + QL_OFF + SW128(r * 128 + c), qlb + (size_t)r * 128 + c);
    }

    auto load_chunk = [&](int j) {
        const int st = j & 1;
        const int f0 = j * 64;
#pragma unroll
        for (int i = 0; i < 2; i++) {
            int e = tid + i * 256;
            int r = e >> 3, c = (e & 7) * 16;
            CP_ASYNC16(sb + KH_OFF + st * 8192 + SW128(r * 128 + c),
                       khb + (size_t)(f0 + r) * 128 + c);
            CP_ASYNC16(sb + KL_OFF + st * 8192 + SW128(r * 128 + c),
                       klb + (size_t)(f0 + r) * 128 + c);
        }
#pragma unroll
        for (int i = 0; i < 4; i++) {
            int e = tid + i * 256;
            int r = e >> 4, c = (e & 15) * 16;
            CP_ASYNC16(sb + VH_OFF + st * 16384 + SW256(r * 256 + c),
                       vhb + (size_t)(f0 + r) * 256 + c);
            CP_ASYNC16(sb + VL_OFF + st * 16384 + SW256(r * 256 + c),
                       vlb + (size_t)(f0 + r) * 256 + c);
        }
    };

    load_chunk(0);
    CP_COMMIT();

    float of[16][4], ob[16][4];
#pragma unroll
    for (int nt = 0; nt < 16; nt++)
#pragma unroll
        for (int e = 0; e < 4; e++) { of[nt][e] = 0.f; ob[nt][e] = 0.f; }

    uint32_t qah[4][4], qal[4][4];
    float rs0 = 0.f, rs1 = 0.f;

    const int arow = lane & 15;
    const int acol = (lane >> 4) * 16;
    const int vrow = ((lane >> 3) & 1) * 8 + (lane & 7);

    for (int j = 0; j < NCHN; j++) {
        __syncthreads();
        if (j + 1 < NCHN) load_chunk(j + 1);
        CP_COMMIT();
        CP_WAIT(1);
        __syncthreads();

        const int st = j & 1;

        if (j == 0) {
#pragma unroll
            for (int k16 = 0; k16 < 4; k16++) {
                uint32_t ah = sb + QH_OFF + SW128((wid*16 + arow) * 128 + k16*32 + acol);
                uint32_t al = sb + QL_OFF + SW128((wid*16 + arow) * 128 + k16*32 + acol);
                LDMATRIX_X4(qah[k16][0], qah[k16][1], qah[k16][2], qah[k16][3], ah);
                LDMATRIX_X4(qal[k16][0], qal[k16][1], qal[k16][2], qal[k16][3], al);
            }
        }

        float s[8][4];
#pragma unroll
        for (int nt = 0; nt < 8; nt++)
#pragma unroll
            for (int e = 0; e < 4; e++) s[nt][e] = 0.f;

        const uint32_t kbh = sb + KH_OFF + st * 8192;
        const uint32_t kbl = sb + KL_OFF + st * 8192;
#pragma unroll
        for (int k16 = 0; k16 < 4; k16++) {
#pragma unroll
            for (int ng = 0; ng < 4; ng++) {
                uint32_t h0, h1, h2, h3, l0, l1, l2, l3;
                uint32_t off = SW128((ng*16 + arow) * 128 + k16*32 + acol);
                LDMATRIX_X4(h0, h1, h2, h3, kbh + off);
                LDMATRIX_X4(l0, l1, l2, l3, kbl + off);
                MMA_BF16S(s[ng*2],   qah[k16], h0, h2);
                MMA_BF16S(s[ng*2+1], qah[k16], h1, h3);
                MMA_BF16S(s[ng*2],   qah[k16], l0, l2);
                MMA_BF16S(s[ng*2+1], qah[k16], l1, l3);
                MMA_BF16S(s[ng*2],   qal[k16], h0, h2);
                MMA_BF16S(s[ng*2+1], qal[k16], h1, h3);
            }
        }

#pragma unroll
        for (int nt = 0; nt < 8; nt++) {
#pragma unroll
            for (int e = 0; e < 4; e++) {
                float p = __expf(fminf(s[nt][e], 88.f) - 16.f);
                s[nt][e] = p;
                if (e < 2) rs0 += p; else rs1 += p;
            }
        }

        const uint32_t vbh = sb + VH_OFF + st * 16384;
        const uint32_t vbl = sb + VL_OFF + st * 16384;
#pragma unroll
        for (int k16 = 0; k16 < 4; k16++) {
            uint32_t ph[4], pl[4];
            {
                float* t0 = s[2*k16];
                float* t1 = s[2*k16 + 1];
                float h00 = __bfloat162float(__float2bfloat16(t0[0]));
                float h01 = __bfloat162float(__float2bfloat16(t0[1]));
                float h02 = __bfloat162float(__float2bfloat16(t0[2]));
                float h03 = __bfloat162float(__float2bfloat16(t0[3]));
                float h10 = __bfloat162float(__float2bfloat16(t1[0]));
                float h11 = __bfloat162float(__float2bfloat16(t1[1]));
                float h12 = __bfloat162float(__float2bfloat16(t1[2]));
                float h13 = __bfloat162float(__float2bfloat16(t1[3]));
                ph[0] = pack_bf16(t0[0], t0[1]);
                ph[1] = pack_bf16(t0[2], t0[3]);
                ph[2] = pack_bf16(t1[0], t1[1]);
                ph[3] = pack_bf16(t1[2], t1[3]);
                pl[0] = pack_bf16(t0[0]-h00, t0[1]-h01);
                pl[1] = pack_bf16(t0[2]-h02, t0[3]-h03);
                pl[2] = pack_bf16(t1[0]-h10, t1[1]-h11);
                pl[3] = pack_bf16(t1[2]-h12, t1[3]-h13);
            }
#pragma unroll
            for (int ng = 0; ng < 8; ng++) {
                uint32_t off = SW256((k16*16 + vrow) * 256 + ng*32 + acol);
                uint32_t vh0, vh1, vh2, vh3, vl0, vl1, vl2, vl3;
                LDMATRIX_X4_T(vh0, vh1, vh2, vh3, vbh + off);
                LDMATRIX_X4_T(vl0, vl1, vl2, vl3, vbl + off);
                MMA_BF16S(ob[ng*2],   ph, vh0, vh1);
                MMA_BF16S(ob[ng*2+1], ph, vh2, vh3);
                MMA_BF16S(ob[ng*2],   ph, vl0, vl1);
                MMA_BF16S(ob[ng*2+1], ph, vl2, vl3);
                MMA_BF16S(ob[ng*2],   pl, vh0, vh1);
                MMA_BF16S(ob[ng*2+1], pl, vh2, vh3);
            }
        }

        if ((j & 7) == 7) {
            rs0 += __shfl_xor_sync(0xffffffffu, rs0, 1);
            rs0 += __shfl_xor_sync(0xffffffffu, rs0, 2);
            rs1 += __shfl_xor_sync(0xffffffffu, rs1, 1);
            rs1 += __shfl_xor_sync(0xffffffffu, rs1, 2);
            float inv0 = 1.f / rs0, inv1 = 1.f / rs1;
#pragma unroll
            for (int nt = 0; nt < 16; nt++) {
                of[nt][0] += ob[nt][0] * inv0;
                of[nt][1] += ob[nt][1] * inv0;
                of[nt][2] += ob[nt][2] * inv1;
                of[nt][3] += ob[nt][3] * inv1;
                ob[nt][0] = 0.f; ob[nt][1] = 0.f; ob[nt][2] = 0.f; ob[nt][3] = 0.f;
            }
            rs0 = 0.f; rs1 = 0.f;
        }
    }

    const int er = lane >> 2, ec = (lane & 3) * 2;
    float* obase = outp + (bh * SS + qr0 + wid*16) * DHH;
#pragma unroll
    for (int nt = 0; nt < 16; nt++) {
        int col = nt*8 + ec;
        float2 o0, o1;
        o0.x = of[nt][0]; o0.y = of[nt][1];
        o1.x = of[nt][2]; o1.y = of[nt][3];
        *(float2*)(obase + (size_t)er * DHH + col)       = o0;
        *(float2*)(obase + (size_t)(er + 8) * DHH + col) = o1;
    }
}

// ---------------------------------------------------------------------------
// Mixer: gelu(attn @ Wm + bm), writing split-stacked bf16 A' directly
// ---------------------------------------------------------------------------
#define MIX_SMEM_BYTES ((128*130 + 16*128) * 4)

__device__ __forceinline__ float gelu_tanh(float x) {
    float x3 = x * x * x;
    return 0.5f * x * (1.f + tanhf(0.7978845608028654f * (x + 0.044715f * x3)));
}

__global__ __launch_bounds__(256)
void mixer_split(const float* __restrict__ attn, const float* __restrict__ Wm,
                 const float* __restrict__ bm, __nv_bfloat16* __restrict__ abf) {
    extern __shared__ float sm[];
    float* wm_s = sm;
    float* in_s = sm + 128*130;

    const int tid = threadIdx.x;
    const int R0 = blockIdx.x * 16;

    for (int i = tid; i < DHH*DHH; i += 256) {
        int d = i >> 7, c = i & 127;
        wm_s[d*130 + c] = Wm[i];
    }
    for (int i = tid; i < 16*DHH; i += 256)
        in_s[i] = attn[(size_t)R0 * DHH + i];
    __syncthreads();

    const int cp = (tid & 63) * 2;
    const int rg = tid >> 6;

    float acc[4][2];
#pragma unroll
    for (int i = 0; i < 4; i++) { acc[i][0] = 0.f; acc[i][1] = 0.f; }

#pragma unroll 8
    for (int d = 0; d < 128; d++) {
        float w0 = wm_s[d*130 + cp], w1 = wm_s[d*130 + cp + 1];
#pragma unroll
        for (int i = 0; i < 4; i++) {
            float a = in_s[(rg*4 + i)*128 + d];
            acc[i][0] += a * w0;
            acc[i][1] += a * w1;
        }
    }

    float b0 = bm[cp], b1 = bm[cp + 1];
#pragma unroll
    for (int i = 0; i < 4; i++) {
        int R = R0 + rg*4 + i;                    // ((b*H + h)*S + s)
        int b = R / (HH*SS);
        int rem = R % (HH*SS);
        int h = rem / SS, s = rem % SS;
        float g0 = gelu_tanh(acc[i][0] + b0);
        float g1 = gelu_tanh(acc[i][1] + b1);
        __nv_bfloat162 hi2, lo2;
        hi2.x = __float2bfloat16(g0);
        hi2.y = __float2bfloat16(g1);
        lo2.x = __float2bfloat16(g0 - __bfloat162float(hi2.x));
        lo2.y = __float2bfloat16(g1 - __bfloat162float(hi2.y));
        size_t rb = ((size_t)b*SS + s) * GK + h*DHH + cp;
        *(__nv_bfloat162*)(abf + rb)        = hi2;   // A hi
        *(__nv_bfloat162*)(abf + rb + 2048) = hi2;   // A hi (dup)
        *(__nv_bfloat162*)(abf + rb + 4096) = lo2;   // A lo
    }
}

// ---------------------------------------------------------------------------
// Launch
// ---------------------------------------------------------------------------
extern "C" void kernel_launch(void* const* d_in, const int* in_sizes, int n_in,
                              void* d_out, int out_size) {
    const float* x   = (const float*)d_in[0];
    const float* Wq  = (const float*)d_in[1];
    const float* bq  = (const float*)d_in[2];
    const float* Wk  = (const float*)d_in[3];
    const float* bk_ = (const float*)d_in[4];
    const float* Wv  = (const float*)d_in[5];
    const float* bv_ = (const float*)d_in[6];
    const float* Wo  = (const float*)d_in[7];
    const float* bo  = (const float*)d_in[8];
    const float* Wql = (const float*)d_in[9];
    const float* bql = (const float*)d_in[10];
    const float* Wkl = (const float*)d_in[11];
    const float* bkl = (const float*)d_in[12];
    const float* Wm  = (const float*)d_in[13];
    const float* bm  = (const float*)d_in[14];
    float* outp = (float*)d_out;

    float* base = nullptr;
    cudaGetSymbolAddress((void**)&base, g_scratch);
    float* attn = base + 3*N_BSE;

    __nv_bfloat16* abf = nullptr;
    cudaGetSymbolAddress((void**)&abf, g_abf);
    __nv_bfloat16* wbf = nullptr;
    cudaGetSymbolAddress((void**)&wbf, g_wbf);
    __nv_bfloat16* wvb = wbf;
    __nv_bfloat16* wob = wbf + (size_t)2048 * GK;
    __nv_bfloat16* wcq = wbf + (size_t)2 * 2048 * GK;   // [1024, 6144]
    __nv_bfloat16* wck = wbf + (size_t)3 * 2048 * GK;

    __nv_bfloat16* qk = nullptr;
    cudaGetSymbolAddress((void**)&qk, g_qk);
    __nv_bfloat16* qh  = qk;
    __nv_bfloat16* ql_ = qk + N_LAT;
    __nv_bfloat16* kh  = qk + 2*N_LAT;
    __nv_bfloat16* kl_ = qk + 3*N_LAT;
    __nv_bfloat16* vp = nullptr;
    cudaGetSymbolAddress((void**)&vp, g_v);
    __nv_bfloat16* vh  = vp;
    __nv_bfloat16* vl_ = vp + N_BSE;

    float* bc = nullptr;
    cudaGetSymbolAddress((void**)&bc, g_bc);
    float* bcq = bc;
    float* bck = bc + 1024;

    cudaFuncSetAttribute(gemm_k<0>,
        cudaFuncAttributeMaxDynamicSharedMemorySize, GEMM_SMEM);
    cudaFuncSetAttribute(gemm_k<1>,
        cudaFuncAttributeMaxDynamicSharedMemorySize, GEMM_SMEM);
    cudaFuncSetAttribute(gemm_k<2>,
        cudaFuncAttributeMaxDynamicSharedMemorySize, GEMM_SMEM);
    cudaFuncSetAttribute(attention_mma,
        cudaFuncAttributeMaxDynamicSharedMemorySize, ATT_SMEM);
    cudaFuncSetAttribute(mixer_split,
        cudaFuncAttributeMaxDynamicSharedMemorySize, MIX_SMEM_BYTES);
    cudaFuncSetAttribute(wc_kernel,
        cudaFuncAttributeMaxDynamicSharedMemorySize, WC_SMEM);

    // input conversions / composed weights
    conv_a<<<MM * 2048 / 1024, 256>>>(x, abf);
    dim3 cwg(64, 64);
    conv_w<<<cwg, 256>>>(Wv, wvb);
    conv_w<<<cwg, 256>>>(Wo, wob);
    wc_kernel<<<dim3(16, 16), 256, WC_SMEM>>>(Wq, Wql, wcq);
    wc_kernel<<<dim3(16, 16), 256, WC_SMEM>>>(Wk, Wkl, wck);
    wc_bias<<<4, 256>>>(bq, Wql, bql, bcq);
    wc_bias<<<4, 256>>>(bk_, Wkl, bkl, bck);

    // projections (V full-width; Q/K composed to latent width with fused elu)
    gemm_k<1><<<dim3(16, 32), 256, GEMM_SMEM>>>(abf, wvb, bv_, nullptr, vh, vl_, 0.f);
    gemm_k<2><<<dim3(8, 32), 256, GEMM_SMEM>>>(abf, wcq, bcq, nullptr, qh, ql_, 0.125f);
    gemm_k<2><<<dim3(8, 32), 256, GEMM_SMEM>>>(abf, wck, bck, nullptr, kh, kl_, 1.0f);

    attention_mma<<<dim3(SS/128, HH, BB), 256, ATT_SMEM>>>(qh, ql_, kh, kl_, vh, vl_, attn);

    mixer_split<<<(BB*HH*SS)/16, 256, MIX_SMEM_BYTES>>>(attn, Wm, bm, abf);

    gemm_k<0><<<dim3(16, 32), 256, GEMM_SMEM>>>(abf, wob, bo, outp, nullptr, nullptr, 0.f);
}